// round 2
// baseline (speedup 1.0000x reference)
#include <cuda_runtime.h>
#include <cstdint>

#define N_I 500000
#define N_H 200000
#define F_I 32
#define F_H 16
#define EF  8

// Per-source-node factored tables: [p0..p7, q, pad, pad, pad] stride 12 floats (48B, float4-aligned)
__device__ __align__(16) float g_tab_h[(size_t)N_H * 12];
__device__ __align__(16) float g_tab_i[(size_t)N_I * 12];

// out[i] = x_indivi[i] . (W_root_h + W_root_i) + bias_h + bias_i
__global__ void init_out_kernel(const float* __restrict__ x,
                                const float* __restrict__ wrh,
                                const float* __restrict__ wri,
                                const float* __restrict__ bh,
                                const float* __restrict__ bi,
                                float* __restrict__ out, int n)
{
    int lane = threadIdx.x & 31;
    int warp = (blockIdx.x * blockDim.x + threadIdx.x) >> 5;
    if (warp >= n) return;
    float w = wrh[lane] + wri[lane];                 // F_I == 32 == warp size
    float v = x[(size_t)warp * F_I + lane] * w;
    #pragma unroll
    for (int o = 16; o; o >>= 1) v += __shfl_xor_sync(0xFFFFFFFFu, v, o);
    if (lane == 0) out[warp] = v + bh[0] + bi[0];
}

// tab[n] = [ x[n] @ W_edge (8 floats), x[n].b_edge, pad... ]
template <int F>
__global__ void precompute_kernel(const float* __restrict__ x,
                                  const float* __restrict__ W,   // [F, 8]
                                  const float* __restrict__ b,   // [F]
                                  float* __restrict__ tab, int n)
{
    __shared__ float Ws[F * EF];
    __shared__ float bs[F];
    for (int t = threadIdx.x; t < F * EF; t += blockDim.x) Ws[t] = W[t];
    for (int t = threadIdx.x; t < F; t += blockDim.x) bs[t] = b[t];
    __syncthreads();

    int i = blockIdx.x * blockDim.x + threadIdx.x;
    if (i >= n) return;

    float p[EF];
    #pragma unroll
    for (int k = 0; k < EF; k++) p[k] = 0.f;
    float q = 0.f;

    const float4* xr = (const float4*)(x + (size_t)i * F);
    #pragma unroll
    for (int f4 = 0; f4 < F / 4; f4++) {
        float4 v = xr[f4];
        float vv[4] = {v.x, v.y, v.z, v.w};
        #pragma unroll
        for (int j = 0; j < 4; j++) {
            int f = f4 * 4 + j;
            q += vv[j] * bs[f];
            #pragma unroll
            for (int k = 0; k < EF; k++) p[k] += vv[j] * Ws[f * EF + k];
        }
    }

    float4* tr = (float4*)(tab + (size_t)i * 12);
    tr[0] = make_float4(p[0], p[1], p[2], p[3]);
    tr[1] = make_float4(p[4], p[5], p[6], p[7]);
    tr[2] = make_float4(q, 0.f, 0.f, 0.f);
}

// msg_e = ea_e . p[src_e] + q[src_e]; atomicAdd(out[dst_e], msg_e)
__global__ void edge_kernel(const float* __restrict__ ea,
                            const int* __restrict__ src,
                            const int* __restrict__ dst,
                            const float* __restrict__ tab,
                            float* __restrict__ out, int E)
{
    int e = blockIdx.x * blockDim.x + threadIdx.x;
    if (e >= E) return;

    const float4* ea4 = (const float4*)ea;
    float4 a = ea4[2 * (size_t)e];
    float4 c = ea4[2 * (size_t)e + 1];
    int s = src[e];
    int d = dst[e];

    const float4* t = (const float4*)tab + (size_t)s * 3;
    float4 p0 = __ldg(t + 0);
    float4 p1 = __ldg(t + 1);
    float  q  = __ldg((const float*)(t + 2));

    float msg = a.x * p0.x + a.y * p0.y + a.z * p0.z + a.w * p0.w
              + c.x * p1.x + c.y * p1.y + c.z * p1.z + c.w * p1.w + q;

    atomicAdd(out + d, msg);
}

extern "C" void kernel_launch(void* const* d_in, const int* in_sizes, int n_in,
                              void* d_out, int out_size)
{
    const float* x_indivi     = (const float*)d_in[0];
    const float* x_house      = (const float*)d_in[1];
    const float* ea_h2i       = (const float*)d_in[2];
    const float* ea_i2i       = (const float*)d_in[3];
    const float* W_edge_h2i   = (const float*)d_in[4];
    const float* b_edge_h2i   = (const float*)d_in[5];
    const float* W_edge_i2i   = (const float*)d_in[6];
    const float* b_edge_i2i   = (const float*)d_in[7];
    const float* W_root_h2i   = (const float*)d_in[8];
    const float* bias_h2i     = (const float*)d_in[9];
    const float* W_root_i2i   = (const float*)d_in[10];
    const float* bias_i2i     = (const float*)d_in[11];
    const int*   src_h2i      = (const int*)d_in[12];
    const int*   dst_h2i      = (const int*)d_in[13];
    const int*   src_i2i      = (const int*)d_in[14];
    const int*   dst_i2i      = (const int*)d_in[15];

    float* out = (float*)d_out;

    const int E1 = in_sizes[12];   // 2,000,000
    const int E2 = in_sizes[14];   // 2,000,000

    float* tab_h = nullptr;
    float* tab_i = nullptr;
    cudaGetSymbolAddress((void**)&tab_h, g_tab_h);
    cudaGetSymbolAddress((void**)&tab_i, g_tab_i);

    // 1) root-term init of out (must precede edge atomics)
    {
        int threads = 256;
        long long total = (long long)N_I * 32;
        int blocks = (int)((total + threads - 1) / threads);
        init_out_kernel<<<blocks, threads>>>(x_indivi, W_root_h2i, W_root_i2i,
                                             bias_h2i, bias_i2i, out, N_I);
    }
    // 2) per-node tables
    {
        int threads = 256;
        precompute_kernel<F_H><<<(N_H + threads - 1) / threads, threads>>>(
            x_house, W_edge_h2i, b_edge_h2i, tab_h, N_H);
        precompute_kernel<F_I><<<(N_I + threads - 1) / threads, threads>>>(
            x_indivi, W_edge_i2i, b_edge_i2i, tab_i, N_I);
    }
    // 3) edge scatter-add
    {
        int threads = 256;
        edge_kernel<<<(E1 + threads - 1) / threads, threads>>>(
            ea_h2i, src_h2i, dst_h2i, tab_h, out, E1);
        edge_kernel<<<(E2 + threads - 1) / threads, threads>>>(
            ea_i2i, src_i2i, dst_i2i, tab_i, out, E2);
    }
}

// round 4
// speedup vs baseline: 1.6028x; 1.6028x over previous
#include <cuda_runtime.h>
#include <cstdint>

#define N_I 500000
#define N_H 200000
#define F_I 32
#define F_H 16
#define EF  8

// Per-source-node factored tables: [p0..p7, q, pad, pad, pad] stride 12 floats (48B)
__device__ __align__(16) float g_tab_h[(size_t)N_H * 12];
__device__ __align__(16) float g_tab_i[(size_t)N_I * 12];

// ---------------------------------------------------------------------------
// Kernel 1: one pass over node features.
//   blocks [0, BI)      : indivi nodes -> tab_i (p[8], q) AND out[i] = x.(wrh+wri)+bias
//   blocks [BI, BI+BH)  : house nodes  -> tab_h (p[8], q)
// ---------------------------------------------------------------------------
__global__ void fused_precompute_kernel(
    const float* __restrict__ x_i, const float* __restrict__ x_h,
    const float* __restrict__ W_i,  const float* __restrict__ b_i,   // [F_I,8],[F_I]
    const float* __restrict__ W_h,  const float* __restrict__ b_h,   // [F_H,8],[F_H]
    const float* __restrict__ wrh,  const float* __restrict__ wri,   // [F_I] each
    const float* __restrict__ bias_h, const float* __restrict__ bias_i,
    float* __restrict__ tab_i, float* __restrict__ tab_h,
    float* __restrict__ out, int BI)
{
    __shared__ float Ws[F_I * EF];   // max size
    __shared__ float bs[F_I];
    __shared__ float wr[F_I];

    if (blockIdx.x < BI) {
        // ---- indivi part ----
        for (int t = threadIdx.x; t < F_I * EF; t += blockDim.x) Ws[t] = W_i[t];
        for (int t = threadIdx.x; t < F_I; t += blockDim.x) {
            bs[t] = b_i[t];
            wr[t] = wrh[t] + wri[t];
        }
        __syncthreads();

        int i = blockIdx.x * blockDim.x + threadIdx.x;
        if (i >= N_I) return;

        float p[EF];
        #pragma unroll
        for (int k = 0; k < EF; k++) p[k] = 0.f;
        float q = 0.f, r = 0.f;

        const float4* xr = (const float4*)(x_i + (size_t)i * F_I);
        #pragma unroll
        for (int f4 = 0; f4 < F_I / 4; f4++) {
            float4 v = xr[f4];
            float vv[4] = {v.x, v.y, v.z, v.w};
            #pragma unroll
            for (int j = 0; j < 4; j++) {
                int f = f4 * 4 + j;
                q += vv[j] * bs[f];
                r += vv[j] * wr[f];
                #pragma unroll
                for (int k = 0; k < EF; k++) p[k] += vv[j] * Ws[f * EF + k];
            }
        }

        float4* tr = (float4*)(tab_i + (size_t)i * 12);
        tr[0] = make_float4(p[0], p[1], p[2], p[3]);
        tr[1] = make_float4(p[4], p[5], p[6], p[7]);
        tr[2] = make_float4(q, 0.f, 0.f, 0.f);
        out[i] = r + bias_h[0] + bias_i[0];
    } else {
        // ---- house part ----
        for (int t = threadIdx.x; t < F_H * EF; t += blockDim.x) Ws[t] = W_h[t];
        for (int t = threadIdx.x; t < F_H; t += blockDim.x) bs[t] = b_h[t];
        __syncthreads();

        int i = (blockIdx.x - BI) * blockDim.x + threadIdx.x;
        if (i >= N_H) return;

        float p[EF];
        #pragma unroll
        for (int k = 0; k < EF; k++) p[k] = 0.f;
        float q = 0.f;

        const float4* xr = (const float4*)(x_h + (size_t)i * F_H);
        #pragma unroll
        for (int f4 = 0; f4 < F_H / 4; f4++) {
            float4 v = xr[f4];
            float vv[4] = {v.x, v.y, v.z, v.w};
            #pragma unroll
            for (int j = 0; j < 4; j++) {
                int f = f4 * 4 + j;
                q += vv[j] * bs[f];
                #pragma unroll
                for (int k = 0; k < EF; k++) p[k] += vv[j] * Ws[f * EF + k];
            }
        }

        float4* tr = (float4*)(tab_h + (size_t)i * 12);
        tr[0] = make_float4(p[0], p[1], p[2], p[3]);
        tr[1] = make_float4(p[4], p[5], p[6], p[7]);
        tr[2] = make_float4(q, 0.f, 0.f, 0.f);
    }
}

// ---------------------------------------------------------------------------
// Kernel 2: both edge relations in one grid.
//   blocks [0, B1)      : h2i edges
//   blocks [B1, B1+B2)  : i2i edges
// Edge streams use evict-first (.cs) so tables/out stay L2-resident.
// ---------------------------------------------------------------------------
__device__ __forceinline__ void edge_work(
    const float* __restrict__ ea, const int* __restrict__ src,
    const int* __restrict__ dst, const float* __restrict__ tab,
    float* __restrict__ out, int e, int E)
{
    if (e >= E) return;

    const float4* ea4 = (const float4*)ea;
    float4 a = __ldcs(ea4 + 2 * (size_t)e);
    float4 c = __ldcs(ea4 + 2 * (size_t)e + 1);
    int s = __ldcs(src + e);
    int d = __ldcs(dst + e);

    const float4* t = (const float4*)tab + (size_t)s * 3;
    float4 p0 = __ldg(t + 0);
    float4 p1 = __ldg(t + 1);
    float  q  = __ldg((const float*)(t + 2));

    float msg = a.x * p0.x + a.y * p0.y + a.z * p0.z + a.w * p0.w
              + c.x * p1.x + c.y * p1.y + c.z * p1.z + c.w * p1.w + q;

    atomicAdd(out + d, msg);
}

__global__ void fused_edge_kernel(
    const float* __restrict__ ea1, const int* __restrict__ src1,
    const int* __restrict__ dst1, const float* __restrict__ tab1, int E1,
    const float* __restrict__ ea2, const int* __restrict__ src2,
    const int* __restrict__ dst2, const float* __restrict__ tab2, int E2,
    float* __restrict__ out, int B1)
{
    if (blockIdx.x < B1) {
        int e = blockIdx.x * blockDim.x + threadIdx.x;
        edge_work(ea1, src1, dst1, tab1, out, e, E1);
    } else {
        int e = (blockIdx.x - B1) * blockDim.x + threadIdx.x;
        edge_work(ea2, src2, dst2, tab2, out, e, E2);
    }
}

extern "C" void kernel_launch(void* const* d_in, const int* in_sizes, int n_in,
                              void* d_out, int out_size)
{
    const float* x_indivi     = (const float*)d_in[0];
    const float* x_house      = (const float*)d_in[1];
    const float* ea_h2i       = (const float*)d_in[2];
    const float* ea_i2i       = (const float*)d_in[3];
    const float* W_edge_h2i   = (const float*)d_in[4];
    const float* b_edge_h2i   = (const float*)d_in[5];
    const float* W_edge_i2i   = (const float*)d_in[6];
    const float* b_edge_i2i   = (const float*)d_in[7];
    const float* W_root_h2i   = (const float*)d_in[8];
    const float* bias_h2i     = (const float*)d_in[9];
    const float* W_root_i2i   = (const float*)d_in[10];
    const float* bias_i2i     = (const float*)d_in[11];
    const int*   src_h2i      = (const int*)d_in[12];
    const int*   dst_h2i      = (const int*)d_in[13];
    const int*   src_i2i      = (const int*)d_in[14];
    const int*   dst_i2i      = (const int*)d_in[15];

    float* out = (float*)d_out;

    const int E1 = in_sizes[12];
    const int E2 = in_sizes[14];

    float* tab_h = nullptr;
    float* tab_i = nullptr;
    cudaGetSymbolAddress((void**)&tab_h, g_tab_h);
    cudaGetSymbolAddress((void**)&tab_i, g_tab_i);

    const int threads = 256;

    // Kernel 1: fused precompute + root init (single pass over node features)
    {
        int BI = (N_I + threads - 1) / threads;
        int BH = (N_H + threads - 1) / threads;
        fused_precompute_kernel<<<BI + BH, threads>>>(
            x_indivi, x_house,
            W_edge_i2i, b_edge_i2i, W_edge_h2i, b_edge_h2i,
            W_root_h2i, W_root_i2i, bias_h2i, bias_i2i,
            tab_i, tab_h, out, BI);
    }
    // Kernel 2: both edge relations
    {
        int B1 = (E1 + threads - 1) / threads;
        int B2 = (E2 + threads - 1) / threads;
        fused_edge_kernel<<<B1 + B2, threads>>>(
            ea_h2i, src_h2i, dst_h2i, tab_h, E1,
            ea_i2i, src_i2i, dst_i2i, tab_i, E2,
            out, B1);
    }
}

// round 5
// speedup vs baseline: 1.9274x; 1.2025x over previous
#include <cuda_runtime.h>
#include <cuda_fp16.h>
#include <cstdint>

#define N_I 500000
#define N_H 200000
#define F_I 32
#define F_H 16
#define EF  8

// Packed per-source-node table entry: 32 bytes, 32B-aligned -> 1 L2 sector.
//   uint4 #0 : 8 x half  (p0..p7)
//   uint4 #1 : float q in .x, rest pad
__device__ __align__(32) uint4 g_tab_h[(size_t)N_H * 2];
__device__ __align__(32) uint4 g_tab_i[(size_t)N_I * 2];

__device__ __forceinline__ unsigned pack2(float a, float b) {
    __half2 h = __floats2half2_rn(a, b);
    return *reinterpret_cast<unsigned*>(&h);
}

// ---------------------------------------------------------------------------
// Kernel 1: one pass over node features; 2 nodes per thread (smem W reuse).
//   blocks [0, BI)      : indivi nodes -> tab_i AND out[i] = x.(wrh+wri)+bias
//   blocks [BI, BI+BH)  : house nodes  -> tab_h
// ---------------------------------------------------------------------------
__global__ void fused_precompute_kernel(
    const float* __restrict__ x_i, const float* __restrict__ x_h,
    const float* __restrict__ W_i,  const float* __restrict__ b_i,
    const float* __restrict__ W_h,  const float* __restrict__ b_h,
    const float* __restrict__ wrh,  const float* __restrict__ wri,
    const float* __restrict__ bias_h, const float* __restrict__ bias_i,
    uint4* __restrict__ tab_i, uint4* __restrict__ tab_h,
    float* __restrict__ out, int BI)
{
    __shared__ float Ws[F_I * EF];
    __shared__ float bs[F_I];
    __shared__ float wr[F_I];

    if (blockIdx.x < BI) {
        // ---- indivi ----
        for (int t = threadIdx.x; t < F_I * EF; t += blockDim.x) Ws[t] = W_i[t];
        for (int t = threadIdx.x; t < F_I; t += blockDim.x) {
            bs[t] = b_i[t];
            wr[t] = wrh[t] + wri[t];
        }
        __syncthreads();

        const int HALF = (N_I + 1) / 2;
        int tgt = blockIdx.x * blockDim.x + threadIdx.x;
        if (tgt >= HALF) return;
        int n0 = tgt;
        int n1 = tgt + HALF;
        bool has1 = (n1 < N_I);

        float p[2][EF];
        float q[2] = {0.f, 0.f}, r[2] = {0.f, 0.f};
        #pragma unroll
        for (int j = 0; j < 2; j++)
            #pragma unroll
            for (int k = 0; k < EF; k++) p[j][k] = 0.f;

        const float4* xr0 = (const float4*)(x_i + (size_t)n0 * F_I);
        const float4* xr1 = (const float4*)(x_i + (size_t)(has1 ? n1 : n0) * F_I);

        #pragma unroll
        for (int f4 = 0; f4 < F_I / 4; f4++) {
            float4 v0 = xr0[f4];
            float4 v1 = xr1[f4];
            float a0[4] = {v0.x, v0.y, v0.z, v0.w};
            float a1[4] = {v1.x, v1.y, v1.z, v1.w};
            #pragma unroll
            for (int j = 0; j < 4; j++) {
                int f = f4 * 4 + j;
                float bsv = bs[f], wrv = wr[f];
                q[0] += a0[j] * bsv;  q[1] += a1[j] * bsv;
                r[0] += a0[j] * wrv;  r[1] += a1[j] * wrv;
                #pragma unroll
                for (int k = 0; k < EF; k++) {
                    float w = Ws[f * EF + k];
                    p[0][k] += a0[j] * w;
                    p[1][k] += a1[j] * w;
                }
            }
        }

        float bb = bias_h[0] + bias_i[0];
        {
            uint4 e0, e1;
            e0.x = pack2(p[0][0], p[0][1]); e0.y = pack2(p[0][2], p[0][3]);
            e0.z = pack2(p[0][4], p[0][5]); e0.w = pack2(p[0][6], p[0][7]);
            e1.x = __float_as_uint(q[0]); e1.y = 0; e1.z = 0; e1.w = 0;
            tab_i[(size_t)n0 * 2]     = e0;
            tab_i[(size_t)n0 * 2 + 1] = e1;
            out[n0] = r[0] + bb;
        }
        if (has1) {
            uint4 e0, e1;
            e0.x = pack2(p[1][0], p[1][1]); e0.y = pack2(p[1][2], p[1][3]);
            e0.z = pack2(p[1][4], p[1][5]); e0.w = pack2(p[1][6], p[1][7]);
            e1.x = __float_as_uint(q[1]); e1.y = 0; e1.z = 0; e1.w = 0;
            tab_i[(size_t)n1 * 2]     = e0;
            tab_i[(size_t)n1 * 2 + 1] = e1;
            out[n1] = r[1] + bb;
        }
    } else {
        // ---- house ----
        for (int t = threadIdx.x; t < F_H * EF; t += blockDim.x) Ws[t] = W_h[t];
        for (int t = threadIdx.x; t < F_H; t += blockDim.x) bs[t] = b_h[t];
        __syncthreads();

        const int HALF = (N_H + 1) / 2;
        int tgt = (blockIdx.x - BI) * blockDim.x + threadIdx.x;
        if (tgt >= HALF) return;
        int n0 = tgt;
        int n1 = tgt + HALF;
        bool has1 = (n1 < N_H);

        float p[2][EF];
        float q[2] = {0.f, 0.f};
        #pragma unroll
        for (int j = 0; j < 2; j++)
            #pragma unroll
            for (int k = 0; k < EF; k++) p[j][k] = 0.f;

        const float4* xr0 = (const float4*)(x_h + (size_t)n0 * F_H);
        const float4* xr1 = (const float4*)(x_h + (size_t)(has1 ? n1 : n0) * F_H);

        #pragma unroll
        for (int f4 = 0; f4 < F_H / 4; f4++) {
            float4 v0 = xr0[f4];
            float4 v1 = xr1[f4];
            float a0[4] = {v0.x, v0.y, v0.z, v0.w};
            float a1[4] = {v1.x, v1.y, v1.z, v1.w};
            #pragma unroll
            for (int j = 0; j < 4; j++) {
                int f = f4 * 4 + j;
                float bsv = bs[f];
                q[0] += a0[j] * bsv;  q[1] += a1[j] * bsv;
                #pragma unroll
                for (int k = 0; k < EF; k++) {
                    float w = Ws[f * EF + k];
                    p[0][k] += a0[j] * w;
                    p[1][k] += a1[j] * w;
                }
            }
        }

        {
            uint4 e0, e1;
            e0.x = pack2(p[0][0], p[0][1]); e0.y = pack2(p[0][2], p[0][3]);
            e0.z = pack2(p[0][4], p[0][5]); e0.w = pack2(p[0][6], p[0][7]);
            e1.x = __float_as_uint(q[0]); e1.y = 0; e1.z = 0; e1.w = 0;
            tab_h[(size_t)n0 * 2]     = e0;
            tab_h[(size_t)n0 * 2 + 1] = e1;
        }
        if (has1) {
            uint4 e0, e1;
            e0.x = pack2(p[1][0], p[1][1]); e0.y = pack2(p[1][2], p[1][3]);
            e0.z = pack2(p[1][4], p[1][5]); e0.w = pack2(p[1][6], p[1][7]);
            e1.x = __float_as_uint(q[1]); e1.y = 0; e1.z = 0; e1.w = 0;
            tab_h[(size_t)n1 * 2]     = e0;
            tab_h[(size_t)n1 * 2 + 1] = e1;
        }
    }
}

// ---------------------------------------------------------------------------
// Kernel 2: both edge relations, 1-sector gather per edge.
// ---------------------------------------------------------------------------
__device__ __forceinline__ void edge_work(
    const float* __restrict__ ea, const int* __restrict__ src,
    const int* __restrict__ dst, const uint4* __restrict__ tab,
    float* __restrict__ out, int e, int E)
{
    if (e >= E) return;

    const float4* ea4 = (const float4*)ea;
    float4 a = __ldcs(ea4 + 2 * (size_t)e);
    float4 c = __ldcs(ea4 + 2 * (size_t)e + 1);
    int s = __ldcs(src + e);
    int d = __ldcs(dst + e);

    uint4 ph = __ldg(tab + (size_t)s * 2);
    float q  = __uint_as_float(__ldg(&(tab + (size_t)s * 2 + 1)->x));

    float2 f0 = __half22float2(*reinterpret_cast<__half2*>(&ph.x));
    float2 f1 = __half22float2(*reinterpret_cast<__half2*>(&ph.y));
    float2 f2 = __half22float2(*reinterpret_cast<__half2*>(&ph.z));
    float2 f3 = __half22float2(*reinterpret_cast<__half2*>(&ph.w));

    float msg = a.x * f0.x + a.y * f0.y + a.z * f1.x + a.w * f1.y
              + c.x * f2.x + c.y * f2.y + c.z * f3.x + c.w * f3.y + q;

    atomicAdd(out + d, msg);
}

__global__ void fused_edge_kernel(
    const float* __restrict__ ea1, const int* __restrict__ src1,
    const int* __restrict__ dst1, const uint4* __restrict__ tab1, int E1,
    const float* __restrict__ ea2, const int* __restrict__ src2,
    const int* __restrict__ dst2, const uint4* __restrict__ tab2, int E2,
    float* __restrict__ out, int B1)
{
    if (blockIdx.x < B1) {
        int e = blockIdx.x * blockDim.x + threadIdx.x;
        edge_work(ea1, src1, dst1, tab1, out, e, E1);
    } else {
        int e = (blockIdx.x - B1) * blockDim.x + threadIdx.x;
        edge_work(ea2, src2, dst2, tab2, out, e, E2);
    }
}

extern "C" void kernel_launch(void* const* d_in, const int* in_sizes, int n_in,
                              void* d_out, int out_size)
{
    const float* x_indivi   = (const float*)d_in[0];
    const float* x_house    = (const float*)d_in[1];
    const float* ea_h2i     = (const float*)d_in[2];
    const float* ea_i2i     = (const float*)d_in[3];
    const float* W_edge_h2i = (const float*)d_in[4];
    const float* b_edge_h2i = (const float*)d_in[5];
    const float* W_edge_i2i = (const float*)d_in[6];
    const float* b_edge_i2i = (const float*)d_in[7];
    const float* W_root_h2i = (const float*)d_in[8];
    const float* bias_h2i   = (const float*)d_in[9];
    const float* W_root_i2i = (const float*)d_in[10];
    const float* bias_i2i   = (const float*)d_in[11];
    const int*   src_h2i    = (const int*)d_in[12];
    const int*   dst_h2i    = (const int*)d_in[13];
    const int*   src_i2i    = (const int*)d_in[14];
    const int*   dst_i2i    = (const int*)d_in[15];

    float* out = (float*)d_out;

    const int E1 = in_sizes[12];
    const int E2 = in_sizes[14];

    uint4* tab_h = nullptr;
    uint4* tab_i = nullptr;
    cudaGetSymbolAddress((void**)&tab_h, g_tab_h);
    cudaGetSymbolAddress((void**)&tab_i, g_tab_i);

    const int threads = 256;

    // Kernel 1: fused precompute + root init (2 nodes per thread)
    {
        int HI = (N_I + 1) / 2;
        int HH = (N_H + 1) / 2;
        int BI = (HI + threads - 1) / threads;
        int BH = (HH + threads - 1) / threads;
        fused_precompute_kernel<<<BI + BH, threads>>>(
            x_indivi, x_house,
            W_edge_i2i, b_edge_i2i, W_edge_h2i, b_edge_h2i,
            W_root_h2i, W_root_i2i, bias_h2i, bias_i2i,
            tab_i, tab_h, out, BI);
    }
    // Kernel 2: both edge relations
    {
        int B1 = (E1 + threads - 1) / threads;
        int B2 = (E2 + threads - 1) / threads;
        fused_edge_kernel<<<B1 + B2, threads>>>(
            ea_h2i, src_h2i, dst_h2i, tab_h, E1,
            ea_i2i, src_i2i, dst_i2i, tab_i, E2,
            out, B1);
    }
}

// round 6
// speedup vs baseline: 1.9390x; 1.0060x over previous
#include <cuda_runtime.h>
#include <cuda_fp16.h>
#include <cstdint>

#define N_I 500000
#define N_H 200000
#define F_I 32
#define F_H 16
#define EF  8

// Packed per-source-node table entry: 32 bytes, 32B-aligned -> 1 L2 sector,
// fetched with a single 256-bit load in the edge kernel.
//   words 0..3 : 8 x half  (p0..p7)
//   word  4    : float q
//   words 5..7 : pad
__device__ __align__(32) uint4 g_tab_h[(size_t)N_H * 2];
__device__ __align__(32) uint4 g_tab_i[(size_t)N_I * 2];

__device__ __forceinline__ unsigned pack2(float a, float b) {
    __half2 h = __floats2half2_rn(a, b);
    return *reinterpret_cast<unsigned*>(&h);
}

// ---------------------------------------------------------------------------
// Kernel 1: one pass over node features; 2 nodes per thread (smem W reuse).
// ---------------------------------------------------------------------------
__global__ void fused_precompute_kernel(
    const float* __restrict__ x_i, const float* __restrict__ x_h,
    const float* __restrict__ W_i,  const float* __restrict__ b_i,
    const float* __restrict__ W_h,  const float* __restrict__ b_h,
    const float* __restrict__ wrh,  const float* __restrict__ wri,
    const float* __restrict__ bias_h, const float* __restrict__ bias_i,
    uint4* __restrict__ tab_i, uint4* __restrict__ tab_h,
    float* __restrict__ out, int BI)
{
    __shared__ float Ws[F_I * EF];
    __shared__ float bs[F_I];
    __shared__ float wr[F_I];

    if (blockIdx.x < BI) {
        // ---- indivi ----
        for (int t = threadIdx.x; t < F_I * EF; t += blockDim.x) Ws[t] = W_i[t];
        for (int t = threadIdx.x; t < F_I; t += blockDim.x) {
            bs[t] = b_i[t];
            wr[t] = wrh[t] + wri[t];
        }
        __syncthreads();

        const int HALF = (N_I + 1) / 2;
        int tgt = blockIdx.x * blockDim.x + threadIdx.x;
        if (tgt >= HALF) return;
        int n0 = tgt;
        int n1 = tgt + HALF;
        bool has1 = (n1 < N_I);

        float p[2][EF];
        float q[2] = {0.f, 0.f}, r[2] = {0.f, 0.f};
        #pragma unroll
        for (int j = 0; j < 2; j++)
            #pragma unroll
            for (int k = 0; k < EF; k++) p[j][k] = 0.f;

        const float4* xr0 = (const float4*)(x_i + (size_t)n0 * F_I);
        const float4* xr1 = (const float4*)(x_i + (size_t)(has1 ? n1 : n0) * F_I);

        #pragma unroll
        for (int f4 = 0; f4 < F_I / 4; f4++) {
            float4 v0 = xr0[f4];
            float4 v1 = xr1[f4];
            float a0[4] = {v0.x, v0.y, v0.z, v0.w};
            float a1[4] = {v1.x, v1.y, v1.z, v1.w};
            #pragma unroll
            for (int j = 0; j < 4; j++) {
                int f = f4 * 4 + j;
                float bsv = bs[f], wrv = wr[f];
                q[0] += a0[j] * bsv;  q[1] += a1[j] * bsv;
                r[0] += a0[j] * wrv;  r[1] += a1[j] * wrv;
                #pragma unroll
                for (int k = 0; k < EF; k++) {
                    float w = Ws[f * EF + k];
                    p[0][k] += a0[j] * w;
                    p[1][k] += a1[j] * w;
                }
            }
        }

        float bb = bias_h[0] + bias_i[0];
        {
            uint4 e0, e1;
            e0.x = pack2(p[0][0], p[0][1]); e0.y = pack2(p[0][2], p[0][3]);
            e0.z = pack2(p[0][4], p[0][5]); e0.w = pack2(p[0][6], p[0][7]);
            e1.x = __float_as_uint(q[0]); e1.y = 0; e1.z = 0; e1.w = 0;
            tab_i[(size_t)n0 * 2]     = e0;
            tab_i[(size_t)n0 * 2 + 1] = e1;
            out[n0] = r[0] + bb;
        }
        if (has1) {
            uint4 e0, e1;
            e0.x = pack2(p[1][0], p[1][1]); e0.y = pack2(p[1][2], p[1][3]);
            e0.z = pack2(p[1][4], p[1][5]); e0.w = pack2(p[1][6], p[1][7]);
            e1.x = __float_as_uint(q[1]); e1.y = 0; e1.z = 0; e1.w = 0;
            tab_i[(size_t)n1 * 2]     = e0;
            tab_i[(size_t)n1 * 2 + 1] = e1;
            out[n1] = r[1] + bb;
        }
    } else {
        // ---- house ----
        for (int t = threadIdx.x; t < F_H * EF; t += blockDim.x) Ws[t] = W_h[t];
        for (int t = threadIdx.x; t < F_H; t += blockDim.x) bs[t] = b_h[t];
        __syncthreads();

        const int HALF = (N_H + 1) / 2;
        int tgt = (blockIdx.x - BI) * blockDim.x + threadIdx.x;
        if (tgt >= HALF) return;
        int n0 = tgt;
        int n1 = tgt + HALF;
        bool has1 = (n1 < N_H);

        float p[2][EF];
        float q[2] = {0.f, 0.f};
        #pragma unroll
        for (int j = 0; j < 2; j++)
            #pragma unroll
            for (int k = 0; k < EF; k++) p[j][k] = 0.f;

        const float4* xr0 = (const float4*)(x_h + (size_t)n0 * F_H);
        const float4* xr1 = (const float4*)(x_h + (size_t)(has1 ? n1 : n0) * F_H);

        #pragma unroll
        for (int f4 = 0; f4 < F_H / 4; f4++) {
            float4 v0 = xr0[f4];
            float4 v1 = xr1[f4];
            float a0[4] = {v0.x, v0.y, v0.z, v0.w};
            float a1[4] = {v1.x, v1.y, v1.z, v1.w};
            #pragma unroll
            for (int j = 0; j < 4; j++) {
                int f = f4 * 4 + j;
                float bsv = bs[f];
                q[0] += a0[j] * bsv;  q[1] += a1[j] * bsv;
                #pragma unroll
                for (int k = 0; k < EF; k++) {
                    float w = Ws[f * EF + k];
                    p[0][k] += a0[j] * w;
                    p[1][k] += a1[j] * w;
                }
            }
        }

        {
            uint4 e0, e1;
            e0.x = pack2(p[0][0], p[0][1]); e0.y = pack2(p[0][2], p[0][3]);
            e0.z = pack2(p[0][4], p[0][5]); e0.w = pack2(p[0][6], p[0][7]);
            e1.x = __float_as_uint(q[0]); e1.y = 0; e1.z = 0; e1.w = 0;
            tab_h[(size_t)n0 * 2]     = e0;
            tab_h[(size_t)n0 * 2 + 1] = e1;
        }
        if (has1) {
            uint4 e0, e1;
            e0.x = pack2(p[1][0], p[1][1]); e0.y = pack2(p[1][2], p[1][3]);
            e0.z = pack2(p[1][4], p[1][5]); e0.w = pack2(p[1][6], p[1][7]);
            e1.x = __float_as_uint(q[1]); e1.y = 0; e1.z = 0; e1.w = 0;
            tab_h[(size_t)n1 * 2]     = e0;
            tab_h[(size_t)n1 * 2 + 1] = e1;
        }
    }
}

// ---------------------------------------------------------------------------
// Kernel 2: both edge relations; single 256-bit gather per edge.
// ---------------------------------------------------------------------------
__device__ __forceinline__ void edge_work(
    const float* __restrict__ ea, const int* __restrict__ src,
    const int* __restrict__ dst, const uint4* __restrict__ tab,
    float* __restrict__ out, int e, int E)
{
    if (e >= E) return;

    const float4* ea4 = (const float4*)ea;
    float4 a = __ldcs(ea4 + 2 * (size_t)e);
    float4 c = __ldcs(ea4 + 2 * (size_t)e + 1);
    int s = __ldcs(src + e);
    int d = __ldcs(dst + e);

    // One LDG.256 grabs the whole 32B entry (8 x half p + fp32 q).
    const void* tp = (const void*)(tab + (size_t)s * 2);
    unsigned r0, r1, r2, r3, r4, r5, r6, r7;
    asm volatile(
        "ld.global.nc.v8.b32 {%0,%1,%2,%3,%4,%5,%6,%7}, [%8];"
        : "=r"(r0), "=r"(r1), "=r"(r2), "=r"(r3),
          "=r"(r4), "=r"(r5), "=r"(r6), "=r"(r7)
        : "l"(tp));

    float2 f0 = __half22float2(*reinterpret_cast<__half2*>(&r0));
    float2 f1 = __half22float2(*reinterpret_cast<__half2*>(&r1));
    float2 f2 = __half22float2(*reinterpret_cast<__half2*>(&r2));
    float2 f3 = __half22float2(*reinterpret_cast<__half2*>(&r3));
    float  q  = __uint_as_float(r4);

    float msg = a.x * f0.x + a.y * f0.y + a.z * f1.x + a.w * f1.y
              + c.x * f2.x + c.y * f2.y + c.z * f3.x + c.w * f3.y + q;

    atomicAdd(out + d, msg);
}

__global__ void fused_edge_kernel(
    const float* __restrict__ ea1, const int* __restrict__ src1,
    const int* __restrict__ dst1, const uint4* __restrict__ tab1, int E1,
    const float* __restrict__ ea2, const int* __restrict__ src2,
    const int* __restrict__ dst2, const uint4* __restrict__ tab2, int E2,
    float* __restrict__ out, int B1)
{
    if (blockIdx.x < B1) {
        int e = blockIdx.x * blockDim.x + threadIdx.x;
        edge_work(ea1, src1, dst1, tab1, out, e, E1);
    } else {
        int e = (blockIdx.x - B1) * blockDim.x + threadIdx.x;
        edge_work(ea2, src2, dst2, tab2, out, e, E2);
    }
}

extern "C" void kernel_launch(void* const* d_in, const int* in_sizes, int n_in,
                              void* d_out, int out_size)
{
    const float* x_indivi   = (const float*)d_in[0];
    const float* x_house    = (const float*)d_in[1];
    const float* ea_h2i     = (const float*)d_in[2];
    const float* ea_i2i     = (const float*)d_in[3];
    const float* W_edge_h2i = (const float*)d_in[4];
    const float* b_edge_h2i = (const float*)d_in[5];
    const float* W_edge_i2i = (const float*)d_in[6];
    const float* b_edge_i2i = (const float*)d_in[7];
    const float* W_root_h2i = (const float*)d_in[8];
    const float* bias_h2i   = (const float*)d_in[9];
    const float* W_root_i2i = (const float*)d_in[10];
    const float* bias_i2i   = (const float*)d_in[11];
    const int*   src_h2i    = (const int*)d_in[12];
    const int*   dst_h2i    = (const int*)d_in[13];
    const int*   src_i2i    = (const int*)d_in[14];
    const int*   dst_i2i    = (const int*)d_in[15];

    float* out = (float*)d_out;

    const int E1 = in_sizes[12];
    const int E2 = in_sizes[14];

    uint4* tab_h = nullptr;
    uint4* tab_i = nullptr;
    cudaGetSymbolAddress((void**)&tab_h, g_tab_h);
    cudaGetSymbolAddress((void**)&tab_i, g_tab_i);

    const int threads = 256;

    // Kernel 1: fused precompute + root init (2 nodes per thread)
    {
        int HI = (N_I + 1) / 2;
        int HH = (N_H + 1) / 2;
        int BI = (HI + threads - 1) / threads;
        int BH = (HH + threads - 1) / threads;
        fused_precompute_kernel<<<BI + BH, threads>>>(
            x_indivi, x_house,
            W_edge_i2i, b_edge_i2i, W_edge_h2i, b_edge_h2i,
            W_root_h2i, W_root_i2i, bias_h2i, bias_i2i,
            tab_i, tab_h, out, BI);
    }
    // Kernel 2: both edge relations
    {
        int B1 = (E1 + threads - 1) / threads;
        int B2 = (E2 + threads - 1) / threads;
        fused_edge_kernel<<<B1 + B2, threads>>>(
            ea_h2i, src_h2i, dst_h2i, tab_h, E1,
            ea_i2i, src_i2i, dst_i2i, tab_i, E2,
            out, B1);
    }
}